// round 11
// baseline (speedup 1.0000x reference)
#include <cuda_runtime.h>

// Lifting wavelet v11: SINGLE kernel (no setup node: ~5us of graph overhead),
// shuffle-halo window (v10: L1 51%), phased arg-tap liveness (v7: only 8 tap
// regs pinned at a time; odd outputs stored before scaling taps are loaded).
// input: (4096, 8192) f32. even = in[:, ::2], odd = in[:, 1::2] (4096 each).
// wavelet[j] = scaling_rec[7-j] * (j odd ? -1 : +1)
// odd_out[k]  = odd[k]  - sum_j wavelet[j] * even[(k-j) mod 4096]
// even_out[k] = even[k] - sum_j scaling[j] * odd[(k-j) mod 4096]
// Output: [even_updated | odd_updated], each 4096x4096 f32.

#define ROWS    4096
#define ROWLEN  8192
#define HALF    4096
#define NTH     256
#define FMASK   (ROWLEN - 1)

__global__ __launch_bounds__(NTH, 5)   // <=51 regs: room for 24-float window +
                                       // 8 phased taps without spilling
void wavelet_fwd_v11(const float* __restrict__ in,
                     const float* __restrict__ scaling,
                     const float* __restrict__ scaling_rec,
                     float* __restrict__ out)
{
    const int g    = blockIdx.x * NTH + threadIdx.x;  // 0 .. 4M-1
    const int row  = g >> 10;                          // 1024 threads per row
    const int lk   = (g & 1023) << 2;                  // pair base: 0..4092
    const int lane = threadIdx.x & 31;

    const float* rowp = in + (size_t)row * ROWLEN;

    // wnd[j] = row[(2lk-16+j) mod 8192], j = 0..23.
    float wnd[24];

    // Own 8 floats: row[2lk .. 2lk+7] -> wnd[16..23]. Amplification 1.0x.
    {
        const float4* p = reinterpret_cast<const float4*>(rowp + 2 * lk);
        float4 v0 = p[0];
        float4 v1 = p[1];
        wnd[16] = v0.x; wnd[17] = v0.y; wnd[18] = v0.z; wnd[19] = v0.w;
        wnd[20] = v1.x; wnd[21] = v1.y; wnd[22] = v1.z; wnd[23] = v1.w;
    }

    // Halo via shuffles (consecutive lanes own consecutive 4-pair segments;
    // blocks never span rows):
    //   lane-1 owns row[2lk-8 .. 2lk-1]  -> wnd[8..15]
    //   lane-2 owns row[2lk-16 .. 2lk-9] -> wnd[0..7]
#pragma unroll
    for (int i = 0; i < 8; i++) {
        wnd[8 + i] = __shfl_up_sync(0xffffffffu, wnd[16 + i], 1);
        wnd[i]     = __shfl_up_sync(0xffffffffu, wnd[16 + i], 2);
    }

    // Lanes 0,1 fix up what shuffles couldn't provide (circular via & FMASK).
    if (lane < 2) {
#pragma unroll
        for (int q = 0; q < 2; q++) {
            int fi = (2 * lk - 16 + 4 * q) & FMASK;
            float4 v = *reinterpret_cast<const float4*>(rowp + fi);
            wnd[4*q+0] = v.x; wnd[4*q+1] = v.y; wnd[4*q+2] = v.z; wnd[4*q+3] = v.w;
        }
        if (lane == 0) {
#pragma unroll
            for (int q = 0; q < 2; q++) {
                int fi = (2 * lk - 8 + 4 * q) & FMASK;
                float4 v = *reinterpret_cast<const float4*>(rowp + fi);
                wnd[8+4*q+0] = v.x; wnd[8+4*q+1] = v.y;
                wnd[8+4*q+2] = v.z; wnd[8+4*q+3] = v.w;
            }
        }
    }

    const size_t obase = (size_t)row * HALF + lk;

    // --- Phase 1: wavelet taps only (8 pinned regs), produce + STORE odd. ---
    {
        float4 r0 = *reinterpret_cast<const float4*>(scaling_rec);
        float4 r1 = *reinterpret_cast<const float4*>(scaling_rec + 4);
        // wavelet[j] = scaling_rec[7-j] * (j odd ? -1 : +1)
        const float w0 =  r1.w, w1 = -r1.z, w2 =  r1.y, w3 = -r1.x;
        const float w4 =  r0.w, w5 = -r0.z, w6 =  r0.y, w7 = -r0.x;
        float rO[4];
#pragma unroll
        for (int m = 0; m < 4; m++) {
            const int b = 2 * m + 16;          // even of pair (lk+m)
            float ce = w0*wnd[b]
                     + w1*wnd[b-2]  + w2*wnd[b-4]  + w3*wnd[b-6]
                     + w4*wnd[b-8]  + w5*wnd[b-10] + w6*wnd[b-12]
                     + w7*wnd[b-14];
            rO[m] = wnd[b + 1] - ce;           // odd - conv(even, wavelet)
        }
        *reinterpret_cast<float4*>(out + (size_t)ROWS * HALF + obase) =
            make_float4(rO[0], rO[1], rO[2], rO[3]);
    }

    // --- Phase 2: scaling taps only, produce + store even. ---
    {
        float4 s0 = *reinterpret_cast<const float4*>(scaling);
        float4 s1 = *reinterpret_cast<const float4*>(scaling + 4);
        const float c0 = s0.x, c1 = s0.y, c2 = s0.z, c3 = s0.w;
        const float c4 = s1.x, c5 = s1.y, c6 = s1.z, c7 = s1.w;
        float rE[4];
#pragma unroll
        for (int m = 0; m < 4; m++) {
            const int b = 2 * m + 16;
            float co = c0*wnd[b+1]
                     + c1*wnd[b-1]  + c2*wnd[b-3]  + c3*wnd[b-5]
                     + c4*wnd[b-7]  + c5*wnd[b-9]  + c6*wnd[b-11]
                     + c7*wnd[b-13];
            rE[m] = wnd[b] - co;               // even - conv(odd, scaling)
        }
        *reinterpret_cast<float4*>(out + obase) =
            make_float4(rE[0], rE[1], rE[2], rE[3]);
    }
}

extern "C" void kernel_launch(void* const* d_in, const int* in_sizes, int n_in,
                              void* d_out, int out_size)
{
    const float* input       = (const float*)d_in[0];
    const float* scaling     = (const float*)d_in[1];
    const float* scaling_rec = (const float*)d_in[2];
    float* out = (float*)d_out;

    const int total_threads = ROWS * (HALF / 4);       // 4M
    wavelet_fwd_v11<<<total_threads / NTH, NTH>>>(input, scaling, scaling_rec, out);
}